// round 2
// baseline (speedup 1.0000x reference)
#include <cuda_runtime.h>

// Output = 1.0f everywhere (analytic reduction: the circuit is diagonal-phase
// gates + CNOT basis permutations acting on |0...0>; the state stays the
// basis state |0...0> (CNOT ring fixes index 0), so <Z_i> = +1 for all wires,
// independent of inputs and weights).
//
// The kernel is pure output fill; at 2 MiB it is launch-overhead bound, so the
// body is branch-free: exact grid, one STG.128 per thread, no loop.

__global__ __launch_bounds__(256) void fill_ones_exact(float4* __restrict__ out) {
    const float4 ones = make_float4(1.0f, 1.0f, 1.0f, 1.0f);
    out[blockIdx.x * 256u + threadIdx.x] = ones;
}

// Generic fallback (guarded grid-stride) for sizes not divisible by 1024 floats.
__global__ __launch_bounds__(256) void fill_ones_generic(float* __restrict__ out, int n) {
    int i = blockIdx.x * 256 + threadIdx.x;
    for (; i < n; i += gridDim.x * 256) out[i] = 1.0f;
}

extern "C" void kernel_launch(void* const* d_in, const int* in_sizes, int n_in,
                              void* d_out, int out_size) {
    (void)d_in; (void)in_sizes; (void)n_in;
    float* out = (float*)d_out;

    // Fast path: out_size divisible by 256 threads * 4 floats = 1024.
    if ((out_size & 1023) == 0 && out_size > 0) {
        int blocks = out_size >> 10;                 // 524288 -> 512 blocks
        fill_ones_exact<<<blocks, 256>>>((float4*)out);
    } else {
        int blocks = (out_size + 255) / 256;
        if (blocks > 1184) blocks = 1184;
        fill_ones_generic<<<blocks, 256>>>(out, out_size);
    }
}

// round 3
// speedup vs baseline: 1.0625x; 1.0625x over previous
#include <cuda_runtime.h>

// Output = 1.0f everywhere (analytic reduction: the circuit is diagonal RZ
// phases + CNOT basis permutations acting on |0...0>; every CNOT fixes basis
// index 0, so the state remains |0...0> up to a global phase and <Z_i> = +1
// for all wires, independent of inputs and weights).
//
// Launch-overhead-bound fill: single wave of 128 CTAs (one per SM, <148),
// 256 threads, 4 independent STG.128 per thread (MLP=4), branch-free.

__global__ __launch_bounds__(256) void fill_ones_x4(float4* __restrict__ out) {
    const float4 ones = make_float4(1.0f, 1.0f, 1.0f, 1.0f);
    // Each CTA owns a contiguous 1024-float4 chunk; each thread 4 float4,
    // strided by 256 within the chunk for coalescing.
    unsigned base = blockIdx.x * 1024u + threadIdx.x;
    out[base]        = ones;
    out[base + 256]  = ones;
    out[base + 512]  = ones;
    out[base + 768]  = ones;
}

// Generic fallback for sizes not divisible by 4096 floats.
__global__ __launch_bounds__(256) void fill_ones_generic(float* __restrict__ out, int n) {
    int i = blockIdx.x * 256 + threadIdx.x;
    for (; i < n; i += gridDim.x * 256) out[i] = 1.0f;
}

extern "C" void kernel_launch(void* const* d_in, const int* in_sizes, int n_in,
                              void* d_out, int out_size) {
    (void)d_in; (void)in_sizes; (void)n_in;
    float* out = (float*)d_out;

    // Fast path: out_size divisible by 256 threads * 4 float4 * 4 floats = 4096.
    if ((out_size & 4095) == 0 && out_size > 0) {
        int blocks = out_size >> 12;                 // 524288 -> 128 blocks
        fill_ones_x4<<<blocks, 256>>>((float4*)out);
    } else {
        int blocks = (out_size + 255) / 256;
        if (blocks > 1184) blocks = 1184;
        fill_ones_generic<<<blocks, 256>>>(out, out_size);
    }
}